// round 15
// baseline (speedup 1.0000x reference)
#include <cuda_runtime.h>

#define EPS 1e-6f

// x: (2048, 4096, 16) fp32  -> 8,388,608 rows of 16 floats (64 B each)
// Grade slices over last dim: [0,1) [1,5) [5,11) [11,15) [15,16)
// out[..., a:b] = x[..., a:b] * rsqrt(sum(x[a:b]^2) + eps) * scale[g]
//
// CONVERGED HBM-streaming kernel: ~6.8 TB/s (85-86% of 8 TB/s spec), the
// measured GB300 ceiling for a 1:1 R/W interleaved stream. Decisive lever:
// sm_103a 256-bit global ld/st (2x ld.global.nc.v8.f32 +
// 2x st.global.v8.f32 per 64B row). This round: scale[5] moved to
// __constant__ (20B D2D memcpy node, capture-legal), cutting per-thread
// LSU ops 9 -> 4 (scale reads use the const port instead of LDG slots).

__constant__ float c_scale[5];

__device__ __forceinline__ void ld256(const float* __restrict__ p, float* r)
{
    asm volatile("ld.global.nc.v8.f32 {%0,%1,%2,%3,%4,%5,%6,%7}, [%8];"
                 : "=f"(r[0]), "=f"(r[1]), "=f"(r[2]), "=f"(r[3]),
                   "=f"(r[4]), "=f"(r[5]), "=f"(r[6]), "=f"(r[7])
                 : "l"(p));
}

__device__ __forceinline__ void st256(float* __restrict__ p, const float* r)
{
    asm volatile("st.global.v8.f32 [%0], {%1,%2,%3,%4,%5,%6,%7,%8};"
                 :: "l"(p),
                    "f"(r[0]), "f"(r[1]), "f"(r[2]), "f"(r[3]),
                    "f"(r[4]), "f"(r[5]), "f"(r[6]), "f"(r[7])
                 : "memory");
}

__global__ void __launch_bounds__(256)
gradewise_ln_kernel(const float* __restrict__ x,
                    float*       __restrict__ out,
                    int nrows)
{
    int row = blockIdx.x * blockDim.x + threadIdx.x;
    if (row >= nrows) return;

    size_t base = (size_t)row * 16;

    float v[16];
    ld256(x + base,     v);
    ld256(x + base + 8, v + 8);

    // grade sums of squares over slices [0,1) [1,5) [5,11) [11,15) [15,16)
    float s0 = v[0] * v[0];
    float s1 = v[1] * v[1] + v[2] * v[2] + v[3] * v[3] + v[4] * v[4];
    float s2 = v[5] * v[5] + v[6] * v[6] + v[7] * v[7]
             + v[8] * v[8] + v[9] * v[9] + v[10] * v[10];
    float s3 = v[11] * v[11] + v[12] * v[12] + v[13] * v[13] + v[14] * v[14];
    float s4 = v[15] * v[15];

    float r0 = rsqrtf(s0 + EPS) * c_scale[0];
    float r1 = rsqrtf(s1 + EPS) * c_scale[1];
    float r2 = rsqrtf(s2 + EPS) * c_scale[2];
    float r3 = rsqrtf(s3 + EPS) * c_scale[3];
    float r4 = rsqrtf(s4 + EPS) * c_scale[4];

    float o[16];
    o[0]  = v[0]  * r0;
    o[1]  = v[1]  * r1;  o[2]  = v[2]  * r1;  o[3]  = v[3]  * r1;
    o[4]  = v[4]  * r1;
    o[5]  = v[5]  * r2;  o[6]  = v[6]  * r2;  o[7]  = v[7]  * r2;
    o[8]  = v[8]  * r2;  o[9]  = v[9]  * r2;  o[10] = v[10] * r2;
    o[11] = v[11] * r3;  o[12] = v[12] * r3;  o[13] = v[13] * r3;
    o[14] = v[14] * r3;
    o[15] = v[15] * r4;

    st256(out + base,     o);
    st256(out + base + 8, o + 8);
}

extern "C" void kernel_launch(void* const* d_in, const int* in_sizes, int n_in,
                              void* d_out, int out_size)
{
    const float* x     = (const float*)d_in[0];
    const float* scale = (const float*)d_in[1];
    float*       out   = (float*)d_out;

    int nrows = in_sizes[0] / 16;  // 2048*4096 = 8,388,608

    // Capture-legal D2D copy of the 5 scales into constant memory
    // (memcpy node; no allocation, no sync).
    cudaMemcpyToSymbolAsync(c_scale, scale, 5 * sizeof(float), 0,
                            cudaMemcpyDeviceToDevice);

    const int threads = 256;
    int blocks = (nrows + threads - 1) / threads;

    gradewise_ln_kernel<<<blocks, threads>>>(x, out, nrows);
}

// round 16
// speedup vs baseline: 1.0168x; 1.0168x over previous
#include <cuda_runtime.h>

#define EPS 1e-6f

// x: (2048, 4096, 16) fp32  -> 8,388,608 rows of 16 floats (64 B each)
// Grade slices over last dim: [0,1) [1,5) [5,11) [11,15) [15,16)
// out[..., a:b] = x[..., a:b] * rsqrt(sum(x[a:b]^2) + eps) * scale[g]
//
// FINAL converged HBM-streaming kernel: ~6.8 TB/s (85-86% of 8 TB/s spec),
// the measured GB300 ceiling for a 1:1 R/W interleaved stream.
// Decisive lever: sm_103a 256-bit global ld/st (2x ld.global.nc.v8.f32 +
// 2x st.global.v8.f32 per 64B row), halving LSU wavefronts vs 128-bit
// (166 -> 157us, DRAM 77 -> 86%). Measured neutral/worse and rejected:
// cache hints (.cs), deeper per-thread MLP, persistent grid-stride,
// occupancy 57-89%, contiguous-vs-strided warp layout, and __constant__
// scale (kernel -1.5us but the extra graph memcpy node cost +1.8us).
// Single kernel node; graph-capturable; allocation-free.

__device__ __forceinline__ void ld256(const float* __restrict__ p, float* r)
{
    asm volatile("ld.global.nc.v8.f32 {%0,%1,%2,%3,%4,%5,%6,%7}, [%8];"
                 : "=f"(r[0]), "=f"(r[1]), "=f"(r[2]), "=f"(r[3]),
                   "=f"(r[4]), "=f"(r[5]), "=f"(r[6]), "=f"(r[7])
                 : "l"(p));
}

__device__ __forceinline__ void st256(float* __restrict__ p, const float* r)
{
    asm volatile("st.global.v8.f32 [%0], {%1,%2,%3,%4,%5,%6,%7,%8};"
                 :: "l"(p),
                    "f"(r[0]), "f"(r[1]), "f"(r[2]), "f"(r[3]),
                    "f"(r[4]), "f"(r[5]), "f"(r[6]), "f"(r[7])
                 : "memory");
}

__global__ void __launch_bounds__(256)
gradewise_ln_kernel(const float* __restrict__ x,
                    const float* __restrict__ scale,
                    float*       __restrict__ out,
                    int nrows)
{
    int row = blockIdx.x * blockDim.x + threadIdx.x;
    if (row >= nrows) return;

    size_t base = (size_t)row * 16;

    float v[16];
    ld256(x + base,     v);
    ld256(x + base + 8, v + 8);

    // grade sums of squares over slices [0,1) [1,5) [5,11) [11,15) [15,16)
    float s0 = v[0] * v[0];
    float s1 = v[1] * v[1] + v[2] * v[2] + v[3] * v[3] + v[4] * v[4];
    float s2 = v[5] * v[5] + v[6] * v[6] + v[7] * v[7]
             + v[8] * v[8] + v[9] * v[9] + v[10] * v[10];
    float s3 = v[11] * v[11] + v[12] * v[12] + v[13] * v[13] + v[14] * v[14];
    float s4 = v[15] * v[15];

    float r0 = rsqrtf(s0 + EPS) * __ldg(&scale[0]);
    float r1 = rsqrtf(s1 + EPS) * __ldg(&scale[1]);
    float r2 = rsqrtf(s2 + EPS) * __ldg(&scale[2]);
    float r3 = rsqrtf(s3 + EPS) * __ldg(&scale[3]);
    float r4 = rsqrtf(s4 + EPS) * __ldg(&scale[4]);

    float o[16];
    o[0]  = v[0]  * r0;
    o[1]  = v[1]  * r1;  o[2]  = v[2]  * r1;  o[3]  = v[3]  * r1;
    o[4]  = v[4]  * r1;
    o[5]  = v[5]  * r2;  o[6]  = v[6]  * r2;  o[7]  = v[7]  * r2;
    o[8]  = v[8]  * r2;  o[9]  = v[9]  * r2;  o[10] = v[10] * r2;
    o[11] = v[11] * r3;  o[12] = v[12] * r3;  o[13] = v[13] * r3;
    o[14] = v[14] * r3;
    o[15] = v[15] * r4;

    st256(out + base,     o);
    st256(out + base + 8, o + 8);
}

extern "C" void kernel_launch(void* const* d_in, const int* in_sizes, int n_in,
                              void* d_out, int out_size)
{
    const float* x     = (const float*)d_in[0];
    const float* scale = (const float*)d_in[1];
    float*       out   = (float*)d_out;

    int nrows = in_sizes[0] / 16;  // 2048*4096 = 8,388,608

    const int threads = 256;
    int blocks = (nrows + threads - 1) / threads;

    gradewise_ln_kernel<<<blocks, threads>>>(x, scale, out, nrows);
}

// round 17
// speedup vs baseline: 1.0170x; 1.0002x over previous
#include <cuda_runtime.h>

#define EPS 1e-6f

// x: (2048, 4096, 16) fp32  -> 8,388,608 rows of 16 floats (64 B each)
// Grade slices over last dim: [0,1) [1,5) [5,11) [11,15) [15,16)
// out[..., a:b] = x[..., a:b] * rsqrt(sum(x[a:b]^2) + eps) * scale[g]
//
// Converged HBM-streaming kernel (~6.8 TB/s, 85-86% of spec = measured
// GB300 ceiling for 1:1 R/W interleaved stream). Shape: one-shot launch,
// 1 row/thread, 2x 256-bit ld + 2x 256-bit st (the decisive R4 lever).
// This round's single variable: ld.global.nc.L2::256B -- promote DRAM
// fetch granularity to 256B per L2 miss. Read stream is perfectly
// sequential so every prefetched byte is demand-used; this can only
// lengthen DRAM read bursts (fewer MC read transactions between write
// batches).

__device__ __forceinline__ void ld256(const float* __restrict__ p, float* r)
{
    asm volatile("ld.global.nc.L2::256B.v8.f32 {%0,%1,%2,%3,%4,%5,%6,%7}, [%8];"
                 : "=f"(r[0]), "=f"(r[1]), "=f"(r[2]), "=f"(r[3]),
                   "=f"(r[4]), "=f"(r[5]), "=f"(r[6]), "=f"(r[7])
                 : "l"(p));
}

__device__ __forceinline__ void st256(float* __restrict__ p, const float* r)
{
    asm volatile("st.global.v8.f32 [%0], {%1,%2,%3,%4,%5,%6,%7,%8};"
                 :: "l"(p),
                    "f"(r[0]), "f"(r[1]), "f"(r[2]), "f"(r[3]),
                    "f"(r[4]), "f"(r[5]), "f"(r[6]), "f"(r[7])
                 : "memory");
}

__global__ void __launch_bounds__(256)
gradewise_ln_kernel(const float* __restrict__ x,
                    const float* __restrict__ scale,
                    float*       __restrict__ out,
                    int nrows)
{
    int row = blockIdx.x * blockDim.x + threadIdx.x;
    if (row >= nrows) return;

    size_t base = (size_t)row * 16;

    float v[16];
    ld256(x + base,     v);
    ld256(x + base + 8, v + 8);

    // grade sums of squares over slices [0,1) [1,5) [5,11) [11,15) [15,16)
    float s0 = v[0] * v[0];
    float s1 = v[1] * v[1] + v[2] * v[2] + v[3] * v[3] + v[4] * v[4];
    float s2 = v[5] * v[5] + v[6] * v[6] + v[7] * v[7]
             + v[8] * v[8] + v[9] * v[9] + v[10] * v[10];
    float s3 = v[11] * v[11] + v[12] * v[12] + v[13] * v[13] + v[14] * v[14];
    float s4 = v[15] * v[15];

    float r0 = rsqrtf(s0 + EPS) * __ldg(&scale[0]);
    float r1 = rsqrtf(s1 + EPS) * __ldg(&scale[1]);
    float r2 = rsqrtf(s2 + EPS) * __ldg(&scale[2]);
    float r3 = rsqrtf(s3 + EPS) * __ldg(&scale[3]);
    float r4 = rsqrtf(s4 + EPS) * __ldg(&scale[4]);

    float o[16];
    o[0]  = v[0]  * r0;
    o[1]  = v[1]  * r1;  o[2]  = v[2]  * r1;  o[3]  = v[3]  * r1;
    o[4]  = v[4]  * r1;
    o[5]  = v[5]  * r2;  o[6]  = v[6]  * r2;  o[7]  = v[7]  * r2;
    o[8]  = v[8]  * r2;  o[9]  = v[9]  * r2;  o[10] = v[10] * r2;
    o[11] = v[11] * r3;  o[12] = v[12] * r3;  o[13] = v[13] * r3;
    o[14] = v[14] * r3;
    o[15] = v[15] * r4;

    st256(out + base,     o);
    st256(out + base + 8, o + 8);
}

extern "C" void kernel_launch(void* const* d_in, const int* in_sizes, int n_in,
                              void* d_out, int out_size)
{
    const float* x     = (const float*)d_in[0];
    const float* scale = (const float*)d_in[1];
    float*       out   = (float*)d_out;

    int nrows = in_sizes[0] / 16;  // 2048*4096 = 8,388,608

    const int threads = 256;
    int blocks = (nrows + threads - 1) / threads;

    gradewise_ln_kernel<<<blocks, threads>>>(x, scale, out, nrows);
}